// round 10
// baseline (speedup 1.0000x reference)
#include <cuda_runtime.h>
#include <cstdint>

typedef unsigned long long ull;

// ---------------- packed f32x2 helpers (Blackwell FFMA2 path) ---------------
__device__ __forceinline__ ull pack2(float lo, float hi) {
    ull r; asm("mov.b64 %0, {%1, %2};" : "=l"(r) : "f"(lo), "f"(hi)); return r;
}
__device__ __forceinline__ ull dup2(float v) {
    ull r; asm("mov.b64 %0, {%1, %1};" : "=l"(r) : "f"(v)); return r;
}
__device__ __forceinline__ void unpack2(ull v, float& lo, float& hi) {
    asm("mov.b64 {%0, %1}, %2;" : "=f"(lo), "=f"(hi) : "l"(v));
}
__device__ __forceinline__ ull fma2(ull a, ull b, ull c) {
    ull d; asm("fma.rn.f32x2 %0, %1, %2, %3;" : "=l"(d) : "l"(a), "l"(b), "l"(c)); return d;
}
__device__ __forceinline__ void cp_async4(unsigned int saddr, const void* gptr, int src_sz) {
    asm volatile("cp.async.ca.shared.global [%0], [%1], 4, %2;"
                 :: "r"(saddr), "l"(gptr), "r"(src_sz));
}
__device__ __forceinline__ void cp_commit() { asm volatile("cp.async.commit_group;"); }
__device__ __forceinline__ void cp_wait0()  { asm volatile("cp.async.wait_group 0;"); }

// ---------------- scratch + sync state (static device globals) --------------
__device__ float g_cA[96 * 256 * 256];          // 25 MB
__device__ int g_next_chunk;
__device__ int g_img_cnt[96];

#define NBLK 296
#define NTILE 1536
#define NCHUNK (96 * 64)                         // 64 chunks per image
#define GRAB 6

__global__ void reset_kernel() {
    int t = threadIdx.x;
    if (t < 96) g_img_cnt[t] = 0;
    if (t == 96) g_next_chunk = 0;
}

// 9-tap accumulate macro: packed weight W applied to 2x2 conv positions
#define K9(W, KY, KX)                                   \
    a0 = fma2(pd[(KY)][(KX)],         (W), a0);         \
    a1 = fma2(pd[(KY)][(KX) + 1],     (W), a1);         \
    a2 = fma2(pd[(KY) + 1][(KX)],     (W), a2);         \
    a3 = fma2(pd[(KY) + 1][(KX) + 1], (W), a3);

// ---------------- Persistent fused kernel: DWT + conv1..conv3 ---------------
// grid 296 (2/SM), block 512. Per tile iteration: (A) grab & run <=GRAB DWT
// chunks (atomic counter, progressive image order), (B) wait tile's cA ready,
// (C) phase1 conv1+pool -> smem t1, (D) gated cp.async prefetch of next cA,
// (E) phase2 conv2+pool, (F) conv3.
__global__ void __launch_bounds__(512, 2)
fused_all_kernel(const float* __restrict__ x,
                 const float* __restrict__ w1, const float* __restrict__ b1,
                 const float* __restrict__ w2, const float* __restrict__ b2,
                 const float* __restrict__ w3, const float* __restrict__ b3,
                 float* __restrict__ out_low, float* __restrict__ out_high) {
    extern __shared__ float sm[];
    float* cAt = sm;                       // 70 * 72 = 5040 floats
    float* ins = sm + 5040;                // 16 * 34 * 36 = 19584 floats
    ull*   w2p = (ull*)(ins + 19584);      // 640 ull (1280 fl)
    ull*   w1p = w2p + 640;                // 80 ull (160 fl)
    float* tail = (float*)(w1p + 80);
    float* b1s = tail;                     // 16
    float* b2s = tail + 16;                // 8
    float* w3s = tail + 24;                // 32
    float* b3s = tail + 56;                // 4
    float* v4buf = tail + 64;              // 2048 floats
    int*   flg = (int*)(tail + 64 + 2048); // [0]=chunk bcast, [1]=prefetch ok

    int tid = threadIdx.x;                               // 512 threads

    // ---- weights (once per block) ----
    if (tid < 80) {
        int op = tid / 10, k = tid - op * 10;
        w1p[tid] = (k < 9) ? pack2(w1[(2 * op) * 9 + k], w1[(2 * op + 1) * 9 + k]) : 0ull;
    }
    for (int i = tid; i < 640; i += 512) {
        int op = i / 160;
        int rem = i - op * 160;            // ic*10 + k
        int ic = rem / 10, k = rem - ic * 10;
        w2p[i] = (k < 9) ? pack2(w2[(2 * op) * 144 + ic * 9 + k],
                                 w2[(2 * op + 1) * 144 + ic * 9 + k]) : 0ull;
    }
    if (tid < 16) b1s[tid] = b1[tid];
    if (tid < 8) b2s[tid] = b2[tid];
    if (tid < 32) w3s[tid] = w3[tid];
    if (tid < 4) b3s[tid] = b3[tid];

    unsigned int cAt_s = (unsigned int)__cvta_generic_to_shared(cAt);

    bool dwt_done = false;
    int pending_load = 1;                  // first tile: direct load path

    for (int tile = blockIdx.x; tile < NTILE; tile += NBLK) {
        int img = tile >> 4;
        int tt = tile & 15;
        int by0 = (tt >> 2) * 32, bx0 = (tt & 3) * 32;

        // ---- (A) DWT service: grab up to GRAB chunks ----
        for (int gi = 0; gi < GRAB && !dwt_done; gi++) {
            if (tid == 0) flg[0] = atomicAdd(&g_next_chunk, 1);
            __syncthreads();
            int c = flg[0];
            if (c >= NCHUNK) { dwt_done = true; break; }
            int cimg = c >> 6;
            int t = ((c & 63) << 9) + tid;               // 0..32767 within img
            int oy = t >> 7;
            int oxp = (t & 127) << 1;
            const float* base = x + (size_t)cimg * 262144 + (size_t)oy * 1024 + 2 * oxp;
            float4 tp = *(const float4*)base;
            float4 bt = *(const float4*)(base + 512);
            float cA0 = (tp.x + tp.y + bt.x + bt.y) * 0.5f;
            float cH0 = (tp.x + tp.y - bt.x - bt.y) * 0.5f;
            float cV0 = (tp.x - tp.y + bt.x - bt.y) * 0.5f;
            float cA1 = (tp.z + tp.w + bt.z + bt.w) * 0.5f;
            float cH1 = (tp.z + tp.w - bt.z - bt.w) * 0.5f;
            float cV1 = (tp.z - tp.w + bt.z - bt.w) * 0.5f;
            int o = oy * 256 + oxp;
            *(float2*)(g_cA + (size_t)cimg * 65536 + o) = make_float2(cA0, cA1);
            float* hb = out_high + (size_t)cimg * 131072;
            *(float2*)(hb + o) = make_float2(cH0, cH1);
            *(float2*)(hb + 65536 + o) = make_float2(cV0, cV1);
            __threadfence();
            __syncthreads();
            if (tid == 0) atomicAdd(&g_img_cnt[cimg], 1);
        }

        // ---- (B) make sure this tile's cA is in cAt ----
        if (pending_load) {
            if (tid == 0) {
                while (*(volatile int*)&g_img_cnt[img] < 64) { }
                __threadfence();
            }
            __syncthreads();
            const float* in = g_cA + (size_t)img * 65536;
            int cy0 = 2 * by0 - 3, cx0 = 2 * bx0 - 3;
            for (int idx = tid; idx < 70 * 70; idx += 512) {
                int r = idx / 70, c = idx - r * 70;
                int gy = cy0 + r, gx = cx0 + c;
                float v = 0.f;
                if ((unsigned)gy < 256u && (unsigned)gx < 256u) v = in[gy * 256 + gx];
                cAt[r * 72 + c] = v;
            }
            __syncthreads();
        } else {
            cp_wait0();
            __syncthreads();
        }

        // ---- (C) phase 1: t1 tile (34x34 positions x 16 ch) ----
        for (int pos = tid; pos < 34 * 34; pos += 512) {
            int r = pos / 34, c = pos - r * 34;
            int ty = by0 - 1 + r, tx = bx0 - 1 + c;
            float* op_out = ins + r * 36 + c;
            if ((unsigned)ty < 128u && (unsigned)tx < 128u) {
                const float* ip = cAt + 2 * r * 72 + 2 * c;
                ull pd[4][4];
#pragma unroll
                for (int rr = 0; rr < 4; rr++) {
                    float2 u0 = *(const float2*)(ip + rr * 72);
                    float2 u1 = *(const float2*)(ip + rr * 72 + 2);
                    pd[rr][0] = dup2(u0.x); pd[rr][1] = dup2(u0.y);
                    pd[rr][2] = dup2(u1.x); pd[rr][3] = dup2(u1.y);
                }
#pragma unroll
                for (int op = 0; op < 8; op++) {
                    ull bb = pack2(b1s[2 * op], b1s[2 * op + 1]);
                    ull a0 = bb, a1 = bb, a2 = bb, a3 = bb;
                    const ull* wp = w1p + op * 10;
                    ulonglong2 w01 = *(const ulonglong2*)wp;
                    ulonglong2 w23 = *(const ulonglong2*)(wp + 2);
                    ulonglong2 w45 = *(const ulonglong2*)(wp + 4);
                    ulonglong2 w67 = *(const ulonglong2*)(wp + 6);
                    ull w8 = wp[8];
                    K9(w01.x, 0, 0) K9(w01.y, 0, 1) K9(w23.x, 0, 2)
                    K9(w23.y, 1, 0) K9(w45.x, 1, 1) K9(w45.y, 1, 2)
                    K9(w67.x, 2, 0) K9(w67.y, 2, 1) K9(w8,    2, 2)
                    float s0l, s0h, s1l, s1h, s2l, s2h, s3l, s3h;
                    unpack2(a0, s0l, s0h); unpack2(a1, s1l, s1h);
                    unpack2(a2, s2l, s2h); unpack2(a3, s3l, s3h);
                    float ml = fmaxf(fmaxf(s0l, s1l), fmaxf(s2l, s3l));
                    float mh = fmaxf(fmaxf(s0h, s1h), fmaxf(s2h, s3h));
                    op_out[(2 * op) * 1224]     = fmaxf(ml, 0.f);
                    op_out[(2 * op + 1) * 1224] = fmaxf(mh, 0.f);
                }
            } else {
#pragma unroll
                for (int ic = 0; ic < 16; ic++) op_out[ic * 1224] = 0.f;
            }
        }
        __syncthreads();                   // ins ready, cAt dead

        // ---- (D) gated prefetch of next tile's cA halo ----
        {
            int nt = tile + NBLK;
            if (nt < NTILE) {
                int nimg = nt >> 4;
                if (tid == 0) flg[1] = (*(volatile int*)&g_img_cnt[nimg] >= 64) ? 1 : 0;
                __syncthreads();
                if (flg[1]) {
                    int ntt = nt & 15;
                    int nby = (ntt >> 2) * 32, nbx = (ntt & 3) * 32;
                    const float* nin = g_cA + (size_t)nimg * 65536;
                    int cy0 = 2 * nby - 3, cx0 = 2 * nbx - 3;
                    for (int idx = tid; idx < 70 * 70; idx += 512) {
                        int r = idx / 70, c = idx - r * 70;
                        int gy = cy0 + r, gx = cx0 + c;
                        bool ok = ((unsigned)gy < 256u) && ((unsigned)gx < 256u);
                        const float* src = ok ? (nin + gy * 256 + gx) : nin;
                        cp_async4(cAt_s + (unsigned int)(r * 72 + c) * 4u, src, ok ? 4 : 0);
                    }
                    pending_load = 0;
                } else {
                    pending_load = 1;
                }
            }
            cp_commit();
        }

        // ---- (E) phase 2: conv2 + relu + pool (oc split across 2 groups) ----
        int pix = tid & 255, g = tid >> 8;
        int tyx = pix & 15, tyy = pix >> 4;
        int ly = 2 * tyy, lx = 2 * tyx;
        ull acc[2][4];
#pragma unroll
        for (int op2 = 0; op2 < 2; op2++) {
            int op = 2 * g + op2;
            ull bb = pack2(b2s[2 * op], b2s[2 * op + 1]);
            acc[op2][0] = bb; acc[op2][1] = bb; acc[op2][2] = bb; acc[op2][3] = bb;
        }

#pragma unroll 1
        for (int ic = 0; ic < 16; ic++) {
            const float* ip = ins + ic * 1224 + ly * 36 + lx;
            ull pd[4][4];
#pragma unroll
            for (int rr = 0; rr < 4; rr++) {
                float2 u0 = *(const float2*)(ip + rr * 36);
                float2 u1 = *(const float2*)(ip + rr * 36 + 2);
                pd[rr][0] = dup2(u0.x); pd[rr][1] = dup2(u0.y);
                pd[rr][2] = dup2(u1.x); pd[rr][3] = dup2(u1.y);
            }
#pragma unroll
            for (int op2 = 0; op2 < 2; op2++) {
                int op = 2 * g + op2;
                const ull* wp = w2p + (op * 16 + ic) * 10;
                ulonglong2 w01 = *(const ulonglong2*)wp;
                ulonglong2 w23 = *(const ulonglong2*)(wp + 2);
                ulonglong2 w45 = *(const ulonglong2*)(wp + 4);
                ulonglong2 w67 = *(const ulonglong2*)(wp + 6);
                ull w8 = wp[8];
                ull a0 = acc[op2][0], a1 = acc[op2][1], a2 = acc[op2][2], a3 = acc[op2][3];
                K9(w01.x, 0, 0) K9(w01.y, 0, 1) K9(w23.x, 0, 2)
                K9(w23.y, 1, 0) K9(w45.x, 1, 1) K9(w45.y, 1, 2)
                K9(w67.x, 2, 0) K9(w67.y, 2, 1) K9(w8,    2, 2)
                acc[op2][0] = a0; acc[op2][1] = a1; acc[op2][2] = a2; acc[op2][3] = a3;
            }
        }

        float v4[4];
#pragma unroll
        for (int op2 = 0; op2 < 2; op2++) {
            float s0l, s0h, s1l, s1h, s2l, s2h, s3l, s3h;
            unpack2(acc[op2][0], s0l, s0h); unpack2(acc[op2][1], s1l, s1h);
            unpack2(acc[op2][2], s2l, s2h); unpack2(acc[op2][3], s3l, s3h);
            float ml = fmaxf(fmaxf(s0l, s1l), fmaxf(s2l, s3l));
            float mh = fmaxf(fmaxf(s0h, s1h), fmaxf(s2h, s3h));
            v4[2 * op2]     = fmaxf(ml, 0.f);
            v4[2 * op2 + 1] = fmaxf(mh, 0.f);
        }
        *(float4*)(v4buf + pix * 8 + 4 * g) = make_float4(v4[0], v4[1], v4[2], v4[3]);
        __syncthreads();

        // ---- (F) conv3 (8->4, 1x1): 512 threads, 2 outputs each ----
        {
            int p = tid >> 1;
            int half = (tid & 1) * 2;
            float4 lo4 = *(const float4*)(v4buf + p * 8);
            float4 hi4 = *(const float4*)(v4buf + p * 8 + 4);
            float v8[8] = {lo4.x, lo4.y, lo4.z, lo4.w, hi4.x, hi4.y, hi4.z, hi4.w};
            int oy = (by0 >> 1) + (p >> 4);
            int ox = (bx0 >> 1) + (p & 15);
            float* ob = out_low + (size_t)img * 4 * 4096 + oy * 64 + ox;
#pragma unroll
            for (int j = 0; j < 2; j++) {
                int o3 = half + j;
                float s = b3s[o3];
#pragma unroll
                for (int ic = 0; ic < 8; ic++) s += v8[ic] * w3s[o3 * 8 + ic];
                ob[o3 * 4096] = s;
            }
        }
        __syncthreads();                  // v4buf/flg reuse safety for next iter
    }
}

// ---------------------------------------------------------------------------
extern "C" void kernel_launch(void* const* d_in, const int* in_sizes, int n_in,
                              void* d_out, int out_size) {
    const float* x  = (const float*)d_in[0];
    const float* w1 = (const float*)d_in[1];
    const float* b1 = (const float*)d_in[2];
    const float* w2 = (const float*)d_in[3];
    const float* b2 = (const float*)d_in[4];
    const float* w3 = (const float*)d_in[5];
    const float* b3 = (const float*)d_in[6];
    float* out = (float*)d_out;

    const int LOW_SIZE = 96 * 4 * 64 * 64;                               // 1,572,864
    const int SMEM_F = (5040 + 19584 + 1280 + 160 + 64 + 2048 + 4) * 4;  // 112,720 B

    cudaFuncSetAttribute(fused_all_kernel, cudaFuncAttributeMaxDynamicSharedMemorySize, SMEM_F);

    reset_kernel<<<1, 128>>>();
    fused_all_kernel<<<NBLK, 512, SMEM_F>>>(x, w1, b1, w2, b2, w3, b3,
                                            out, out + LOW_SIZE);
}

// round 11
// speedup vs baseline: 1.0926x; 1.0926x over previous
#include <cuda_runtime.h>
#include <cstdint>

typedef unsigned long long ull;

// ---------------- packed f32x2 helpers (Blackwell FFMA2 path) ---------------
__device__ __forceinline__ ull pack2(float lo, float hi) {
    ull r; asm("mov.b64 %0, {%1, %2};" : "=l"(r) : "f"(lo), "f"(hi)); return r;
}
__device__ __forceinline__ ull dup2(float v) {
    ull r; asm("mov.b64 %0, {%1, %1};" : "=l"(r) : "f"(v)); return r;
}
__device__ __forceinline__ void unpack2(ull v, float& lo, float& hi) {
    asm("mov.b64 {%0, %1}, %2;" : "=f"(lo), "=f"(hi) : "l"(v));
}
__device__ __forceinline__ ull fma2(ull a, ull b, ull c) {
    ull d; asm("fma.rn.f32x2 %0, %1, %2, %3;" : "=l"(d) : "l"(a), "l"(b), "l"(c)); return d;
}

// 9-tap accumulate macro: packed weight W applied to 2x2 conv positions
#define K9(W, KY, KX)                                   \
    a0 = fma2(pd[(KY)][(KX)],         (W), a0);         \
    a1 = fma2(pd[(KY)][(KX) + 1],     (W), a1);         \
    a2 = fma2(pd[(KY) + 1][(KX)],     (W), a2);         \
    a3 = fma2(pd[(KY) + 1][(KX) + 1], (W), a3);

#define NBLK 296
#define NTILE 1536

// ---------------- Single persistent fused kernel ----------------------------
// grid 296 (2/SM), block 512. Per tile iteration:
//   phase 0: Haar DWT from x -> cAt smem (70x70 halo) + write own 64x64 cH/cV
//   phase 1: conv1+relu+pool -> smem t1 (34x34x16)
//   phase 2: conv2+relu+pool (oc split over 2 groups)
//   phase 3: conv3 (1x1)
__global__ void __launch_bounds__(512, 2)
fused_all_kernel(const float* __restrict__ x,
                 const float* __restrict__ w1, const float* __restrict__ b1,
                 const float* __restrict__ w2, const float* __restrict__ b2,
                 const float* __restrict__ w3, const float* __restrict__ b3,
                 float* __restrict__ out_low, float* __restrict__ out_high) {
    extern __shared__ float sm[];
    float* cAt = sm;                       // 70 * 72 = 5040 floats
    float* ins = sm + 5040;                // 16 * 34 * 36 = 19584 floats
    ull*   w2p = (ull*)(ins + 19584);      // 640 ull (1280 fl)
    ull*   w1p = w2p + 640;                // 80 ull (160 fl)
    float* tail = (float*)(w1p + 80);
    float* b1s = tail;                     // 16
    float* b2s = tail + 16;                // 8
    float* w3s = tail + 24;                // 32
    float* b3s = tail + 56;                // 4
    float* v4buf = tail + 64;              // 2048 floats

    int tid = threadIdx.x;                               // 512 threads

    // ---- weights (once per block) ----
    if (tid < 80) {
        int op = tid / 10, k = tid - op * 10;
        w1p[tid] = (k < 9) ? pack2(w1[(2 * op) * 9 + k], w1[(2 * op + 1) * 9 + k]) : 0ull;
    }
    for (int i = tid; i < 640; i += 512) {
        int op = i / 160;
        int rem = i - op * 160;            // ic*10 + k
        int ic = rem / 10, k = rem - ic * 10;
        w2p[i] = (k < 9) ? pack2(w2[(2 * op) * 144 + ic * 9 + k],
                                 w2[(2 * op + 1) * 144 + ic * 9 + k]) : 0ull;
    }
    if (tid < 16) b1s[tid] = b1[tid];
    if (tid < 8) b2s[tid] = b2[tid];
    if (tid < 32) w3s[tid] = w3[tid];
    if (tid < 4) b3s[tid] = b3[tid];
    __syncthreads();

    for (int tile = blockIdx.x; tile < NTILE; tile += NBLK) {
        int img = tile >> 4;
        int tt = tile & 15;
        int by0 = (tt >> 2) * 32, bx0 = (tt & 3) * 32;   // conv2 origin in 128x128

        // ---- phase 0: Haar DWT from x into cAt + own cH/cV region ----
        {
            int cy0 = 2 * by0 - 3, cx0 = 2 * bx0 - 3;     // cA halo origin in 256x256
            const float* xb = x + (size_t)img * 262144;
            float* hb = out_high + (size_t)img * 131072;
            for (int idx = tid; idx < 70 * 70; idx += 512) {
                int r = idx / 70, c = idx - r * 70;
                int oy = cy0 + r, ox = cx0 + c;
                float a = 0.f, b = 0.f, cc = 0.f, d = 0.f;
                if ((unsigned)oy < 256u && (unsigned)ox < 256u) {
                    const float* bp = xb + (size_t)(2 * oy) * 512 + 2 * ox;
                    float2 t = *(const float2*)bp;
                    float2 bo = *(const float2*)(bp + 512);
                    a = t.x; b = t.y; cc = bo.x; d = bo.y;
                }
                float cA = (a + b + cc + d) * 0.5f;
                cAt[r * 72 + c] = cA;
                if (r >= 3 && r < 67 && c >= 3 && c < 67) {
                    int o = oy * 256 + ox;
                    hb[o]         = (a + b - cc - d) * 0.5f;
                    hb[65536 + o] = (a - b + cc - d) * 0.5f;
                }
            }
        }
        __syncthreads();                   // cAt ready; prior-tile v4buf free

        // ---- phase 1: t1 tile (34x34 positions x 16 ch) ----
        for (int pos = tid; pos < 34 * 34; pos += 512) {
            int r = pos / 34, c = pos - r * 34;
            int ty = by0 - 1 + r, tx = bx0 - 1 + c;       // global t1 coords
            float* op_out = ins + r * 36 + c;
            if ((unsigned)ty < 128u && (unsigned)tx < 128u) {
                const float* ip = cAt + 2 * r * 72 + 2 * c;
                ull pd[4][4];
#pragma unroll
                for (int rr = 0; rr < 4; rr++) {
                    float2 u0 = *(const float2*)(ip + rr * 72);
                    float2 u1 = *(const float2*)(ip + rr * 72 + 2);
                    pd[rr][0] = dup2(u0.x); pd[rr][1] = dup2(u0.y);
                    pd[rr][2] = dup2(u1.x); pd[rr][3] = dup2(u1.y);
                }
#pragma unroll
                for (int op = 0; op < 8; op++) {
                    ull bb = pack2(b1s[2 * op], b1s[2 * op + 1]);
                    ull a0 = bb, a1 = bb, a2 = bb, a3 = bb;
                    const ull* wp = w1p + op * 10;
                    ulonglong2 w01 = *(const ulonglong2*)wp;
                    ulonglong2 w23 = *(const ulonglong2*)(wp + 2);
                    ulonglong2 w45 = *(const ulonglong2*)(wp + 4);
                    ulonglong2 w67 = *(const ulonglong2*)(wp + 6);
                    ull w8 = wp[8];
                    K9(w01.x, 0, 0) K9(w01.y, 0, 1) K9(w23.x, 0, 2)
                    K9(w23.y, 1, 0) K9(w45.x, 1, 1) K9(w45.y, 1, 2)
                    K9(w67.x, 2, 0) K9(w67.y, 2, 1) K9(w8,    2, 2)
                    float s0l, s0h, s1l, s1h, s2l, s2h, s3l, s3h;
                    unpack2(a0, s0l, s0h); unpack2(a1, s1l, s1h);
                    unpack2(a2, s2l, s2h); unpack2(a3, s3l, s3h);
                    float ml = fmaxf(fmaxf(s0l, s1l), fmaxf(s2l, s3l));
                    float mh = fmaxf(fmaxf(s0h, s1h), fmaxf(s2h, s3h));
                    op_out[(2 * op) * 1224]     = fmaxf(ml, 0.f);
                    op_out[(2 * op + 1) * 1224] = fmaxf(mh, 0.f);
                }
            } else {
#pragma unroll
                for (int ic = 0; ic < 16; ic++) op_out[ic * 1224] = 0.f;
            }
        }
        __syncthreads();                   // ins ready, cAt dead

        // ---- phase 2: conv2 + relu + pool (oc split across 2 groups) ----
        int pix = tid & 255, g = tid >> 8;
        int tyx = pix & 15, tyy = pix >> 4;
        int ly = 2 * tyy, lx = 2 * tyx;
        ull acc[2][4];
#pragma unroll
        for (int op2 = 0; op2 < 2; op2++) {
            int op = 2 * g + op2;
            ull bb = pack2(b2s[2 * op], b2s[2 * op + 1]);
            acc[op2][0] = bb; acc[op2][1] = bb; acc[op2][2] = bb; acc[op2][3] = bb;
        }

#pragma unroll 1
        for (int ic = 0; ic < 16; ic++) {
            const float* ip = ins + ic * 1224 + ly * 36 + lx;
            ull pd[4][4];
#pragma unroll
            for (int rr = 0; rr < 4; rr++) {
                float2 u0 = *(const float2*)(ip + rr * 36);
                float2 u1 = *(const float2*)(ip + rr * 36 + 2);
                pd[rr][0] = dup2(u0.x); pd[rr][1] = dup2(u0.y);
                pd[rr][2] = dup2(u1.x); pd[rr][3] = dup2(u1.y);
            }
#pragma unroll
            for (int op2 = 0; op2 < 2; op2++) {
                int op = 2 * g + op2;
                const ull* wp = w2p + (op * 16 + ic) * 10;
                ulonglong2 w01 = *(const ulonglong2*)wp;
                ulonglong2 w23 = *(const ulonglong2*)(wp + 2);
                ulonglong2 w45 = *(const ulonglong2*)(wp + 4);
                ulonglong2 w67 = *(const ulonglong2*)(wp + 6);
                ull w8 = wp[8];
                ull a0 = acc[op2][0], a1 = acc[op2][1], a2 = acc[op2][2], a3 = acc[op2][3];
                K9(w01.x, 0, 0) K9(w01.y, 0, 1) K9(w23.x, 0, 2)
                K9(w23.y, 1, 0) K9(w45.x, 1, 1) K9(w45.y, 1, 2)
                K9(w67.x, 2, 0) K9(w67.y, 2, 1) K9(w8,    2, 2)
                acc[op2][0] = a0; acc[op2][1] = a1; acc[op2][2] = a2; acc[op2][3] = a3;
            }
        }

        float v4[4];
#pragma unroll
        for (int op2 = 0; op2 < 2; op2++) {
            float s0l, s0h, s1l, s1h, s2l, s2h, s3l, s3h;
            unpack2(acc[op2][0], s0l, s0h); unpack2(acc[op2][1], s1l, s1h);
            unpack2(acc[op2][2], s2l, s2h); unpack2(acc[op2][3], s3l, s3h);
            float ml = fmaxf(fmaxf(s0l, s1l), fmaxf(s2l, s3l));
            float mh = fmaxf(fmaxf(s0h, s1h), fmaxf(s2h, s3h));
            v4[2 * op2]     = fmaxf(ml, 0.f);
            v4[2 * op2 + 1] = fmaxf(mh, 0.f);
        }
        *(float4*)(v4buf + pix * 8 + 4 * g) = make_float4(v4[0], v4[1], v4[2], v4[3]);
        __syncthreads();

        // ---- phase 3: conv3 (8->4, 1x1): 512 threads, 2 outputs each ----
        {
            int p = tid >> 1;                    // pixel 0..255
            int half = (tid & 1) * 2;            // o3 in {half, half+1}
            float4 lo4 = *(const float4*)(v4buf + p * 8);
            float4 hi4 = *(const float4*)(v4buf + p * 8 + 4);
            float v8[8] = {lo4.x, lo4.y, lo4.z, lo4.w, hi4.x, hi4.y, hi4.z, hi4.w};
            int oy = (by0 >> 1) + (p >> 4);
            int ox = (bx0 >> 1) + (p & 15);
            float* ob = out_low + (size_t)img * 4 * 4096 + oy * 64 + ox;
#pragma unroll
            for (int j = 0; j < 2; j++) {
                int o3 = half + j;
                float s = b3s[o3];
#pragma unroll
                for (int ic = 0; ic < 8; ic++) s += v8[ic] * w3s[o3 * 8 + ic];
                ob[o3 * 4096] = s;
            }
        }
        // no sync needed: next phase 0 writes only cAt (not read in ph2/3);
        // the phase0->phase1 sync orders everything else.
    }
}

// ---------------------------------------------------------------------------
extern "C" void kernel_launch(void* const* d_in, const int* in_sizes, int n_in,
                              void* d_out, int out_size) {
    const float* x  = (const float*)d_in[0];
    const float* w1 = (const float*)d_in[1];
    const float* b1 = (const float*)d_in[2];
    const float* w2 = (const float*)d_in[3];
    const float* b2 = (const float*)d_in[4];
    const float* w3 = (const float*)d_in[5];
    const float* b3 = (const float*)d_in[6];
    float* out = (float*)d_out;

    const int LOW_SIZE = 96 * 4 * 64 * 64;                               // 1,572,864
    const int SMEM_F = (5040 + 19584 + 1280 + 160 + 64 + 2048) * 4;      // 112,704 B

    cudaFuncSetAttribute(fused_all_kernel, cudaFuncAttributeMaxDynamicSharedMemorySize, SMEM_F);

    fused_all_kernel<<<NBLK, 512, SMEM_F>>>(x, w1, b1, w2, b2, w3, b3,
                                            out, out + LOW_SIZE);
}

// round 12
// speedup vs baseline: 1.1557x; 1.0578x over previous
#include <cuda_runtime.h>
#include <cstdint>

typedef unsigned long long ull;

// ---------------- packed f32x2 helpers (Blackwell FFMA2 path) ---------------
__device__ __forceinline__ ull pack2(float lo, float hi) {
    ull r; asm("mov.b64 %0, {%1, %2};" : "=l"(r) : "f"(lo), "f"(hi)); return r;
}
__device__ __forceinline__ ull dup2(float v) {
    ull r; asm("mov.b64 %0, {%1, %1};" : "=l"(r) : "f"(v)); return r;
}
__device__ __forceinline__ void unpack2(ull v, float& lo, float& hi) {
    asm("mov.b64 {%0, %1}, %2;" : "=f"(lo), "=f"(hi) : "l"(v));
}
__device__ __forceinline__ ull fma2(ull a, ull b, ull c) {
    ull d; asm("fma.rn.f32x2 %0, %1, %2, %3;" : "=l"(d) : "l"(a), "l"(b), "l"(c)); return d;
}
__device__ __forceinline__ void cp_async16(unsigned int saddr, const void* gptr, int src_sz) {
    asm volatile("cp.async.cg.shared.global [%0], [%1], 16, %2;"
                 :: "r"(saddr), "l"(gptr), "r"(src_sz));
}
__device__ __forceinline__ void cp_commit() { asm volatile("cp.async.commit_group;"); }
__device__ __forceinline__ void cp_wait0()  { asm volatile("cp.async.wait_group 0;"); }

// 9-tap accumulate macro: packed weight W applied to 2x2 conv positions
#define K9(W, KY, KX)                                   \
    a0 = fma2(pd[(KY)][(KX)],         (W), a0);         \
    a1 = fma2(pd[(KY)][(KX) + 1],     (W), a1);         \
    a2 = fma2(pd[(KY) + 1][(KX)],     (W), a2);         \
    a3 = fma2(pd[(KY) + 1][(KX) + 1], (W), a3);

#define NBLK 296
#define NTILE 1536

// x-halo staging prefetch for tile (img, by0, bx0) into xst (140 rows x 144 cols).
// Row r covers x row ry0+r; 36 16B chunks per row from col xc0a.
// All chunks fully in-bounds or fully OOB (zero-filled) -- no straddles.
#define PREFETCH_X(IMG, BY0, BX0)                                             \
    {                                                                         \
        const float* xb = x + (size_t)(IMG) * 262144;                         \
        int ry0 = 4 * (BY0) - 6;                                              \
        int xc0a = (4 * (BX0) - 6) & ~3;                                      \
        for (int idx = tid; idx < 140 * 36; idx += 512) {                     \
            int rr = idx / 36, j = idx - rr * 36;                             \
            int gr = ry0 + rr, gc = xc0a + 4 * j;                             \
            bool ok = ((unsigned)gr < 512u) && ((unsigned)gc < 512u);         \
            const float* src = ok ? (xb + (size_t)gr * 512 + gc) : xb;        \
            cp_async16(xst_s + (unsigned int)(rr * 144 + 4 * j) * 4u, src,    \
                       ok ? 16 : 0);                                          \
        }                                                                     \
        cp_commit();                                                          \
    }

// ---------------- Single persistent fused kernel ----------------------------
// grid 296 (2/SM), block 512. Per tile iteration:
//   wait xst -> phase 0: DWT xst->cAt (+ own 64x64 cH/cV to gmem)
//   phase 1: conv1+relu+pool -> ins (overwrites xst region)
//   phase 2: conv2+relu+pool; then prefetch next x tile into ins; conv3.
__global__ void __launch_bounds__(512, 2)
fused_all_kernel(const float* __restrict__ x,
                 const float* __restrict__ w1, const float* __restrict__ b1,
                 const float* __restrict__ w2, const float* __restrict__ b2,
                 const float* __restrict__ w3, const float* __restrict__ b3,
                 float* __restrict__ out_low, float* __restrict__ out_high) {
    extern __shared__ float sm[];
    float* cAt = sm;                       // 70 * 72 = 5040 floats
    float* ins = sm + 5040;                // max(140*144, 16*1224) = 20160 floats
    float* xst = ins;                      // x staging aliases ins
    ull*   w2p = (ull*)(ins + 20160);      // 640 ull (1280 fl)
    ull*   w1p = w2p + 640;                // 80 ull (160 fl)
    float* tail = (float*)(w1p + 80);
    float* b1s = tail;                     // 16
    float* b2s = tail + 16;                // 8
    float* w3s = tail + 24;                // 32
    float* b3s = tail + 56;                // 4
    float* v4buf = tail + 64;              // 2048 floats

    int tid = threadIdx.x;                               // 512 threads
    unsigned int xst_s = (unsigned int)__cvta_generic_to_shared(xst);

    // ---- prologue prefetch for first tile ----
    {
        int tile0 = blockIdx.x;
        int img0 = tile0 >> 4;
        int tt0 = tile0 & 15;
        int by00 = (tt0 >> 2) * 32, bx00 = (tt0 & 3) * 32;
        PREFETCH_X(img0, by00, bx00)
    }

    // ---- weights (once per block) ----
    if (tid < 80) {
        int op = tid / 10, k = tid - op * 10;
        w1p[tid] = (k < 9) ? pack2(w1[(2 * op) * 9 + k], w1[(2 * op + 1) * 9 + k]) : 0ull;
    }
    for (int i = tid; i < 640; i += 512) {
        int op = i / 160;
        int rem = i - op * 160;            // ic*10 + k
        int ic = rem / 10, k = rem - ic * 10;
        w2p[i] = (k < 9) ? pack2(w2[(2 * op) * 144 + ic * 9 + k],
                                 w2[(2 * op + 1) * 144 + ic * 9 + k]) : 0ull;
    }
    if (tid < 16) b1s[tid] = b1[tid];
    if (tid < 8) b2s[tid] = b2[tid];
    if (tid < 32) w3s[tid] = w3[tid];
    if (tid < 4) b3s[tid] = b3[tid];

    for (int tile = blockIdx.x; tile < NTILE; tile += NBLK) {
        int img = tile >> 4;
        int tt = tile & 15;
        int by0 = (tt >> 2) * 32, bx0 = (tt & 3) * 32;   // conv2 origin in 128x128
        int cy0 = 2 * by0 - 3, cx0 = 2 * bx0 - 3;        // cA halo origin in 256x256

        cp_wait0();
        __syncthreads();                   // xst staged; weights ready (iter 0)

        // ---- phase 0: Haar DWT from xst -> cAt + own cH/cV region ----
        {
            float* hb = out_high + (size_t)img * 131072;
            for (int idx = tid; idx < 70 * 70; idx += 512) {
                int r = idx / 70, c = idx - r * 70;
                // x rows 2r,2r+1; col offset 2c + 2 (delta=2 constant)
                const float* bp = xst + 2 * r * 144 + 2 * c + 2;
                float2 t = *(const float2*)bp;
                float2 bo = *(const float2*)(bp + 144);
                float a = t.x, b = t.y, cc = bo.x, d = bo.y;
                cAt[r * 72 + c] = (a + b + cc + d) * 0.5f;
                if (r >= 3 && r < 67 && c >= 3 && c < 67) {
                    int o = (cy0 + r) * 256 + (cx0 + c);
                    hb[o]         = (a + b - cc - d) * 0.5f;
                    hb[65536 + o] = (a - b + cc - d) * 0.5f;
                }
            }
        }
        __syncthreads();                   // cAt ready; xst consumed

        // ---- phase 1: t1 tile (34x34 positions x 16 ch) -> ins ----
        for (int pos = tid; pos < 34 * 34; pos += 512) {
            int r = pos / 34, c = pos - r * 34;
            int ty = by0 - 1 + r, tx = bx0 - 1 + c;       // global t1 coords
            float* op_out = ins + r * 36 + c;
            if ((unsigned)ty < 128u && (unsigned)tx < 128u) {
                const float* ip = cAt + 2 * r * 72 + 2 * c;
                ull pd[4][4];
#pragma unroll
                for (int rr = 0; rr < 4; rr++) {
                    float2 u0 = *(const float2*)(ip + rr * 72);
                    float2 u1 = *(const float2*)(ip + rr * 72 + 2);
                    pd[rr][0] = dup2(u0.x); pd[rr][1] = dup2(u0.y);
                    pd[rr][2] = dup2(u1.x); pd[rr][3] = dup2(u1.y);
                }
#pragma unroll
                for (int op = 0; op < 8; op++) {
                    ull bb = pack2(b1s[2 * op], b1s[2 * op + 1]);
                    ull a0 = bb, a1 = bb, a2 = bb, a3 = bb;
                    const ull* wp = w1p + op * 10;
                    ulonglong2 w01 = *(const ulonglong2*)wp;
                    ulonglong2 w23 = *(const ulonglong2*)(wp + 2);
                    ulonglong2 w45 = *(const ulonglong2*)(wp + 4);
                    ulonglong2 w67 = *(const ulonglong2*)(wp + 6);
                    ull w8 = wp[8];
                    K9(w01.x, 0, 0) K9(w01.y, 0, 1) K9(w23.x, 0, 2)
                    K9(w23.y, 1, 0) K9(w45.x, 1, 1) K9(w45.y, 1, 2)
                    K9(w67.x, 2, 0) K9(w67.y, 2, 1) K9(w8,    2, 2)
                    float s0l, s0h, s1l, s1h, s2l, s2h, s3l, s3h;
                    unpack2(a0, s0l, s0h); unpack2(a1, s1l, s1h);
                    unpack2(a2, s2l, s2h); unpack2(a3, s3l, s3h);
                    float ml = fmaxf(fmaxf(s0l, s1l), fmaxf(s2l, s3l));
                    float mh = fmaxf(fmaxf(s0h, s1h), fmaxf(s2h, s3h));
                    op_out[(2 * op) * 1224]     = fmaxf(ml, 0.f);
                    op_out[(2 * op + 1) * 1224] = fmaxf(mh, 0.f);
                }
            } else {
#pragma unroll
                for (int ic = 0; ic < 16; ic++) op_out[ic * 1224] = 0.f;
            }
        }
        __syncthreads();                   // ins ready

        // ---- phase 2: conv2 + relu + pool (oc split across 2 groups) ----
        int pix = tid & 255, g = tid >> 8;
        int tyx = pix & 15, tyy = pix >> 4;
        int ly = 2 * tyy, lx = 2 * tyx;
        ull acc[2][4];
#pragma unroll
        for (int op2 = 0; op2 < 2; op2++) {
            int op = 2 * g + op2;
            ull bb = pack2(b2s[2 * op], b2s[2 * op + 1]);
            acc[op2][0] = bb; acc[op2][1] = bb; acc[op2][2] = bb; acc[op2][3] = bb;
        }

#pragma unroll 1
        for (int ic = 0; ic < 16; ic++) {
            const float* ip = ins + ic * 1224 + ly * 36 + lx;
            ull pd[4][4];
#pragma unroll
            for (int rr = 0; rr < 4; rr++) {
                float2 u0 = *(const float2*)(ip + rr * 36);
                float2 u1 = *(const float2*)(ip + rr * 36 + 2);
                pd[rr][0] = dup2(u0.x); pd[rr][1] = dup2(u0.y);
                pd[rr][2] = dup2(u1.x); pd[rr][3] = dup2(u1.y);
            }
#pragma unroll
            for (int op2 = 0; op2 < 2; op2++) {
                int op = 2 * g + op2;
                const ull* wp = w2p + (op * 16 + ic) * 10;
                ulonglong2 w01 = *(const ulonglong2*)wp;
                ulonglong2 w23 = *(const ulonglong2*)(wp + 2);
                ulonglong2 w45 = *(const ulonglong2*)(wp + 4);
                ulonglong2 w67 = *(const ulonglong2*)(wp + 6);
                ull w8 = wp[8];
                ull a0 = acc[op2][0], a1 = acc[op2][1], a2 = acc[op2][2], a3 = acc[op2][3];
                K9(w01.x, 0, 0) K9(w01.y, 0, 1) K9(w23.x, 0, 2)
                K9(w23.y, 1, 0) K9(w45.x, 1, 1) K9(w45.y, 1, 2)
                K9(w67.x, 2, 0) K9(w67.y, 2, 1) K9(w8,    2, 2)
                acc[op2][0] = a0; acc[op2][1] = a1; acc[op2][2] = a2; acc[op2][3] = a3;
            }
        }

        float v4[4];
#pragma unroll
        for (int op2 = 0; op2 < 2; op2++) {
            float s0l, s0h, s1l, s1h, s2l, s2h, s3l, s3h;
            unpack2(acc[op2][0], s0l, s0h); unpack2(acc[op2][1], s1l, s1h);
            unpack2(acc[op2][2], s2l, s2h); unpack2(acc[op2][3], s3l, s3h);
            float ml = fmaxf(fmaxf(s0l, s1l), fmaxf(s2l, s3l));
            float mh = fmaxf(fmaxf(s0h, s1h), fmaxf(s2h, s3h));
            v4[2 * op2]     = fmaxf(ml, 0.f);
            v4[2 * op2 + 1] = fmaxf(mh, 0.f);
        }
        *(float4*)(v4buf + pix * 8 + 4 * g) = make_float4(v4[0], v4[1], v4[2], v4[3]);
        __syncthreads();                   // phase 2 fully done; ins now dead

        // ---- prefetch next tile's x halo into ins (overlaps conv3) ----
        {
            int nt = tile + NBLK;
            if (nt < NTILE) {
                int nimg = nt >> 4;
                int ntt = nt & 15;
                int nby = (ntt >> 2) * 32, nbx = (ntt & 3) * 32;
                PREFETCH_X(nimg, nby, nbx)
            } else {
                cp_commit();
            }
        }

        // ---- phase 3: conv3 (8->4, 1x1): 512 threads, 2 outputs each ----
        {
            int p = tid >> 1;                    // pixel 0..255
            int half = (tid & 1) * 2;            // o3 in {half, half+1}
            float4 lo4 = *(const float4*)(v4buf + p * 8);
            float4 hi4 = *(const float4*)(v4buf + p * 8 + 4);
            float v8[8] = {lo4.x, lo4.y, lo4.z, lo4.w, hi4.x, hi4.y, hi4.z, hi4.w};
            int oy = (by0 >> 1) + (p >> 4);
            int ox = (bx0 >> 1) + (p & 15);
            float* ob = out_low + (size_t)img * 4 * 4096 + oy * 64 + ox;
#pragma unroll
            for (int j = 0; j < 2; j++) {
                int o3 = half + j;
                float s = b3s[o3];
#pragma unroll
                for (int ic = 0; ic < 8; ic++) s += v8[ic] * w3s[o3 * 8 + ic];
                ob[o3 * 4096] = s;
            }
        }
        // loop top: cp_wait0 + syncthreads orders xst staging & v4buf reuse
    }
}

// ---------------------------------------------------------------------------
extern "C" void kernel_launch(void* const* d_in, const int* in_sizes, int n_in,
                              void* d_out, int out_size) {
    const float* x  = (const float*)d_in[0];
    const float* w1 = (const float*)d_in[1];
    const float* b1 = (const float*)d_in[2];
    const float* w2 = (const float*)d_in[3];
    const float* b2 = (const float*)d_in[4];
    const float* w3 = (const float*)d_in[5];
    const float* b3 = (const float*)d_in[6];
    float* out = (float*)d_out;

    const int LOW_SIZE = 96 * 4 * 64 * 64;                               // 1,572,864
    const int SMEM_F = (5040 + 20160 + 1280 + 160 + 64 + 2048) * 4;      // 115,008 B

    cudaFuncSetAttribute(fused_all_kernel, cudaFuncAttributeMaxDynamicSharedMemorySize, SMEM_F);

    fused_all_kernel<<<NBLK, 512, SMEM_F>>>(x, w1, b1, w2, b2, w3, b3,
                                            out, out + LOW_SIZE);
}

// round 13
// speedup vs baseline: 1.1813x; 1.0221x over previous
#include <cuda_runtime.h>
#include <cstdint>

typedef unsigned long long ull;

// ---------------- packed f32x2 helpers (Blackwell FFMA2 path) ---------------
__device__ __forceinline__ ull pack2(float lo, float hi) {
    ull r; asm("mov.b64 %0, {%1, %2};" : "=l"(r) : "f"(lo), "f"(hi)); return r;
}
__device__ __forceinline__ ull dup2(float v) {
    ull r; asm("mov.b64 %0, {%1, %1};" : "=l"(r) : "f"(v)); return r;
}
__device__ __forceinline__ void unpack2(ull v, float& lo, float& hi) {
    asm("mov.b64 {%0, %1}, %2;" : "=f"(lo), "=f"(hi) : "l"(v));
}
__device__ __forceinline__ ull fma2(ull a, ull b, ull c) {
    ull d; asm("fma.rn.f32x2 %0, %1, %2, %3;" : "=l"(d) : "l"(a), "l"(b), "l"(c)); return d;
}
__device__ __forceinline__ void cp_async16(unsigned int saddr, const void* gptr, int src_sz) {
    asm volatile("cp.async.cg.shared.global [%0], [%1], 16, %2;"
                 :: "r"(saddr), "l"(gptr), "r"(src_sz));
}
__device__ __forceinline__ void cp_commit() { asm volatile("cp.async.commit_group;"); }
__device__ __forceinline__ void cp_wait0()  { asm volatile("cp.async.wait_group 0;"); }

// 9-tap accumulate macro: packed weight W applied to 2x2 conv positions
#define K9(W, KY, KX)                                   \
    a0 = fma2(pd[(KY)][(KX)],         (W), a0);         \
    a1 = fma2(pd[(KY)][(KX) + 1],     (W), a1);         \
    a2 = fma2(pd[(KY) + 1][(KX)],     (W), a2);         \
    a3 = fma2(pd[(KY) + 1][(KX) + 1], (W), a3);

#define NBLK 296
#define NTILE 1536

// ---------------- dynamic tile queue ----------------------------------------
__device__ int g_ctr;
__global__ void reset_kernel() { if (threadIdx.x == 0) g_ctr = 0; }

// x-halo staging prefetch for tile (img, by0, bx0) into xst (140 rows x 144 cols).
// All 16B chunks fully in-bounds or fully OOB (zero-filled) -- no straddles.
#define PREFETCH_X(IMG, BY0, BX0)                                             \
    {                                                                         \
        const float* xb = x + (size_t)(IMG) * 262144;                         \
        int ry0 = 4 * (BY0) - 6;                                              \
        int xc0a = (4 * (BX0) - 6) & ~3;                                      \
        for (int idx = tid; idx < 140 * 36; idx += 512) {                     \
            int rr = idx / 36, j = idx - rr * 36;                             \
            int gr = ry0 + rr, gc = xc0a + 4 * j;                             \
            bool ok = ((unsigned)gr < 512u) && ((unsigned)gc < 512u);         \
            const float* src = ok ? (xb + (size_t)gr * 512 + gc) : xb;        \
            cp_async16(xst_s + (unsigned int)(rr * 144 + 4 * j) * 4u, src,    \
                       ok ? 16 : 0);                                          \
        }                                                                     \
        cp_commit();                                                          \
    }

// ---------------- Single persistent fused kernel ----------------------------
// grid 296 (2/SM), block 512. Dynamic tile claiming via g_ctr.
// Per tile: wait xst -> phase0 DWT (xst->cAt + own cH/cV) -> phase1 conv1+pool
// -> ins -> phase2 conv2+pool (claims next tile during) -> prefetch next x
// -> conv3.
__global__ void __launch_bounds__(512, 2)
fused_all_kernel(const float* __restrict__ x,
                 const float* __restrict__ w1, const float* __restrict__ b1,
                 const float* __restrict__ w2, const float* __restrict__ b2,
                 const float* __restrict__ w3, const float* __restrict__ b3,
                 float* __restrict__ out_low, float* __restrict__ out_high) {
    extern __shared__ float sm[];
    float* cAt = sm;                       // 70 * 72 = 5040 floats
    float* ins = sm + 5040;                // max(140*144, 16*1224) = 20160 floats
    float* xst = ins;                      // x staging aliases ins
    ull*   w2p = (ull*)(ins + 20160);      // 640 ull (1280 fl)
    ull*   w1p = w2p + 640;                // 80 ull (160 fl)
    float* tail = (float*)(w1p + 80);
    float* b1s = tail;                     // 16
    float* b2s = tail + 16;                // 8
    float* w3s = tail + 24;                // 32
    float* b3s = tail + 56;                // 4
    float* v4buf = tail + 64;              // 2048 floats
    int*   flg = (int*)(tail + 64 + 2048); // [0]=initial claim, [1]=next claim

    int tid = threadIdx.x;                               // 512 threads
    unsigned int xst_s = (unsigned int)__cvta_generic_to_shared(xst);

    // ---- initial tile claim ----
    if (tid == 0) flg[0] = atomicAdd(&g_ctr, 1);
    __syncthreads();
    int tile = flg[0];

    // ---- prologue prefetch for first tile ----
    if (tile < NTILE) {
        int img0 = tile >> 4;
        int tt0 = tile & 15;
        int by00 = (tt0 >> 2) * 32, bx00 = (tt0 & 3) * 32;
        PREFETCH_X(img0, by00, bx00)
    }

    // ---- weights (once per block) ----
    if (tid < 80) {
        int op = tid / 10, k = tid - op * 10;
        w1p[tid] = (k < 9) ? pack2(w1[(2 * op) * 9 + k], w1[(2 * op + 1) * 9 + k]) : 0ull;
    }
    for (int i = tid; i < 640; i += 512) {
        int op = i / 160;
        int rem = i - op * 160;            // ic*10 + k
        int ic = rem / 10, k = rem - ic * 10;
        w2p[i] = (k < 9) ? pack2(w2[(2 * op) * 144 + ic * 9 + k],
                                 w2[(2 * op + 1) * 144 + ic * 9 + k]) : 0ull;
    }
    if (tid < 16) b1s[tid] = b1[tid];
    if (tid < 8) b2s[tid] = b2[tid];
    if (tid < 32) w3s[tid] = w3[tid];
    if (tid < 4) b3s[tid] = b3[tid];

    while (tile < NTILE) {
        int img = tile >> 4;
        int tt = tile & 15;
        int by0 = (tt >> 2) * 32, bx0 = (tt & 3) * 32;   // conv2 origin in 128x128
        int cy0 = 2 * by0 - 3, cx0 = 2 * bx0 - 3;        // cA halo origin in 256x256

        cp_wait0();
        __syncthreads();                   // (a) xst staged; v4buf/flg free

        // ---- phase 0: Haar DWT from xst -> cAt + own cH/cV region ----
        {
            float* hb = out_high + (size_t)img * 131072;
            for (int idx = tid; idx < 70 * 70; idx += 512) {
                int r = idx / 70, c = idx - r * 70;
                const float* bp = xst + 2 * r * 144 + 2 * c + 2;
                float2 t = *(const float2*)bp;
                float2 bo = *(const float2*)(bp + 144);
                float a = t.x, b = t.y, cc = bo.x, d = bo.y;
                cAt[r * 72 + c] = (a + b + cc + d) * 0.5f;
                if (r >= 3 && r < 67 && c >= 3 && c < 67) {
                    int o = (cy0 + r) * 256 + (cx0 + c);
                    hb[o]         = (a + b - cc - d) * 0.5f;
                    hb[65536 + o] = (a - b + cc - d) * 0.5f;
                }
            }
        }
        __syncthreads();                   // (b) cAt ready; xst consumed

        // ---- phase 1: t1 tile (34x34 positions x 16 ch) -> ins ----
        for (int pos = tid; pos < 34 * 34; pos += 512) {
            int r = pos / 34, c = pos - r * 34;
            int ty = by0 - 1 + r, tx = bx0 - 1 + c;       // global t1 coords
            float* op_out = ins + r * 36 + c;
            if ((unsigned)ty < 128u && (unsigned)tx < 128u) {
                const float* ip = cAt + 2 * r * 72 + 2 * c;
                ull pd[4][4];
#pragma unroll
                for (int rr = 0; rr < 4; rr++) {
                    float2 u0 = *(const float2*)(ip + rr * 72);
                    float2 u1 = *(const float2*)(ip + rr * 72 + 2);
                    pd[rr][0] = dup2(u0.x); pd[rr][1] = dup2(u0.y);
                    pd[rr][2] = dup2(u1.x); pd[rr][3] = dup2(u1.y);
                }
#pragma unroll
                for (int op = 0; op < 8; op++) {
                    ull bb = pack2(b1s[2 * op], b1s[2 * op + 1]);
                    ull a0 = bb, a1 = bb, a2 = bb, a3 = bb;
                    const ull* wp = w1p + op * 10;
                    ulonglong2 w01 = *(const ulonglong2*)wp;
                    ulonglong2 w23 = *(const ulonglong2*)(wp + 2);
                    ulonglong2 w45 = *(const ulonglong2*)(wp + 4);
                    ulonglong2 w67 = *(const ulonglong2*)(wp + 6);
                    ull w8 = wp[8];
                    K9(w01.x, 0, 0) K9(w01.y, 0, 1) K9(w23.x, 0, 2)
                    K9(w23.y, 1, 0) K9(w45.x, 1, 1) K9(w45.y, 1, 2)
                    K9(w67.x, 2, 0) K9(w67.y, 2, 1) K9(w8,    2, 2)
                    float s0l, s0h, s1l, s1h, s2l, s2h, s3l, s3h;
                    unpack2(a0, s0l, s0h); unpack2(a1, s1l, s1h);
                    unpack2(a2, s2l, s2h); unpack2(a3, s3l, s3h);
                    float ml = fmaxf(fmaxf(s0l, s1l), fmaxf(s2l, s3l));
                    float mh = fmaxf(fmaxf(s0h, s1h), fmaxf(s2h, s3h));
                    op_out[(2 * op) * 1224]     = fmaxf(ml, 0.f);
                    op_out[(2 * op + 1) * 1224] = fmaxf(mh, 0.f);
                }
            } else {
#pragma unroll
                for (int ic = 0; ic < 16; ic++) op_out[ic * 1224] = 0.f;
            }
        }
        __syncthreads();                   // (c) ins ready

        // ---- claim next tile (latency hidden under phase 2) ----
        if (tid == 0) flg[1] = atomicAdd(&g_ctr, 1);

        // ---- phase 2: conv2 + relu + pool (oc split across 2 groups) ----
        int pix = tid & 255, g = tid >> 8;
        int tyx = pix & 15, tyy = pix >> 4;
        int ly = 2 * tyy, lx = 2 * tyx;
        const ull* wg = w2p + (2 * g) * 160;
        ull acc[2][4];
#pragma unroll
        for (int op2 = 0; op2 < 2; op2++) {
            int op = 2 * g + op2;
            ull bb = pack2(b2s[2 * op], b2s[2 * op + 1]);
            acc[op2][0] = bb; acc[op2][1] = bb; acc[op2][2] = bb; acc[op2][3] = bb;
        }

#pragma unroll 1
        for (int ic = 0; ic < 16; ic++) {
            const float* ip = ins + ic * 1224 + ly * 36 + lx;
            ull pd[4][4];
#pragma unroll
            for (int rr = 0; rr < 4; rr++) {
                float2 u0 = *(const float2*)(ip + rr * 36);
                float2 u1 = *(const float2*)(ip + rr * 36 + 2);
                pd[rr][0] = dup2(u0.x); pd[rr][1] = dup2(u0.y);
                pd[rr][2] = dup2(u1.x); pd[rr][3] = dup2(u1.y);
            }
#pragma unroll
            for (int op2 = 0; op2 < 2; op2++) {
                const ull* wp = wg + op2 * 160 + ic * 10;
                ulonglong2 w01 = *(const ulonglong2*)wp;
                ulonglong2 w23 = *(const ulonglong2*)(wp + 2);
                ulonglong2 w45 = *(const ulonglong2*)(wp + 4);
                ulonglong2 w67 = *(const ulonglong2*)(wp + 6);
                ull w8 = wp[8];
                ull a0 = acc[op2][0], a1 = acc[op2][1], a2 = acc[op2][2], a3 = acc[op2][3];
                K9(w01.x, 0, 0) K9(w01.y, 0, 1) K9(w23.x, 0, 2)
                K9(w23.y, 1, 0) K9(w45.x, 1, 1) K9(w45.y, 1, 2)
                K9(w67.x, 2, 0) K9(w67.y, 2, 1) K9(w8,    2, 2)
                acc[op2][0] = a0; acc[op2][1] = a1; acc[op2][2] = a2; acc[op2][3] = a3;
            }
        }

        float v4[4];
#pragma unroll
        for (int op2 = 0; op2 < 2; op2++) {
            float s0l, s0h, s1l, s1h, s2l, s2h, s3l, s3h;
            unpack2(acc[op2][0], s0l, s0h); unpack2(acc[op2][1], s1l, s1h);
            unpack2(acc[op2][2], s2l, s2h); unpack2(acc[op2][3], s3l, s3h);
            float ml = fmaxf(fmaxf(s0l, s1l), fmaxf(s2l, s3l));
            float mh = fmaxf(fmaxf(s0h, s1h), fmaxf(s2h, s3h));
            v4[2 * op2]     = fmaxf(ml, 0.f);
            v4[2 * op2 + 1] = fmaxf(mh, 0.f);
        }
        *(float4*)(v4buf + pix * 8 + 4 * g) = make_float4(v4[0], v4[1], v4[2], v4[3]);
        __syncthreads();                   // (d) ins dead; v4buf + flg[1] ready

        int ntile = flg[1];

        // ---- prefetch next tile's x halo into ins (overlaps conv3) ----
        if (ntile < NTILE) {
            int nimg = ntile >> 4;
            int ntt = ntile & 15;
            int nby = (ntt >> 2) * 32, nbx = (ntt & 3) * 32;
            PREFETCH_X(nimg, nby, nbx)
        }

        // ---- phase 3: conv3 (8->4, 1x1): 512 threads, 2 outputs each ----
        {
            int p = tid >> 1;                    // pixel 0..255
            int half = (tid & 1) * 2;            // o3 in {half, half+1}
            float4 lo4 = *(const float4*)(v4buf + p * 8);
            float4 hi4 = *(const float4*)(v4buf + p * 8 + 4);
            float v8[8] = {lo4.x, lo4.y, lo4.z, lo4.w, hi4.x, hi4.y, hi4.z, hi4.w};
            int oy = (by0 >> 1) + (p >> 4);
            int ox = (bx0 >> 1) + (p & 15);
            float* ob = out_low + (size_t)img * 4 * 4096 + oy * 64 + ox;
#pragma unroll
            for (int j = 0; j < 2; j++) {
                int o3 = half + j;
                float s = b3s[o3];
#pragma unroll
                for (int ic = 0; ic < 8; ic++) s += v8[ic] * w3s[o3 * 8 + ic];
                ob[o3 * 4096] = s;
            }
        }

        tile = ntile;
        // loop top: cp_wait0 + syncthreads orders xst staging & v4buf reuse
    }
}

// ---------------------------------------------------------------------------
extern "C" void kernel_launch(void* const* d_in, const int* in_sizes, int n_in,
                              void* d_out, int out_size) {
    const float* x  = (const float*)d_in[0];
    const float* w1 = (const float*)d_in[1];
    const float* b1 = (const float*)d_in[2];
    const float* w2 = (const float*)d_in[3];
    const float* b2 = (const float*)d_in[4];
    const float* w3 = (const float*)d_in[5];
    const float* b3 = (const float*)d_in[6];
    float* out = (float*)d_out;

    const int LOW_SIZE = 96 * 4 * 64 * 64;                               // 1,572,864
    const int SMEM_F = (5040 + 20160 + 1280 + 160 + 64 + 2048 + 4) * 4;  // 115,024 B

    cudaFuncSetAttribute(fused_all_kernel, cudaFuncAttributeMaxDynamicSharedMemorySize, SMEM_F);

    reset_kernel<<<1, 32>>>();
    fused_all_kernel<<<NBLK, 512, SMEM_F>>>(x, w1, b1, w2, b2, w3, b3,
                                            out, out + LOW_SIZE);
}

// round 14
// speedup vs baseline: 1.1860x; 1.0039x over previous
#include <cuda_runtime.h>
#include <cstdint>

typedef unsigned long long ull;

// ---------------- packed f32x2 helpers (Blackwell FFMA2 path) ---------------
__device__ __forceinline__ ull pack2(float lo, float hi) {
    ull r; asm("mov.b64 %0, {%1, %2};" : "=l"(r) : "f"(lo), "f"(hi)); return r;
}
__device__ __forceinline__ ull dup2(float v) {
    ull r; asm("mov.b64 %0, {%1, %1};" : "=l"(r) : "f"(v)); return r;
}
__device__ __forceinline__ void unpack2(ull v, float& lo, float& hi) {
    asm("mov.b64 {%0, %1}, %2;" : "=f"(lo), "=f"(hi) : "l"(v));
}
__device__ __forceinline__ ull fma2(ull a, ull b, ull c) {
    ull d; asm("fma.rn.f32x2 %0, %1, %2, %3;" : "=l"(d) : "l"(a), "l"(b), "l"(c)); return d;
}
__device__ __forceinline__ void cp_async16(unsigned int saddr, const void* gptr, int src_sz) {
    asm volatile("cp.async.cg.shared.global [%0], [%1], 16, %2;"
                 :: "r"(saddr), "l"(gptr), "r"(src_sz));
}
__device__ __forceinline__ void cp_commit() { asm volatile("cp.async.commit_group;"); }
__device__ __forceinline__ void cp_wait0()  { asm volatile("cp.async.wait_group 0;"); }

// 9-tap accumulate macro: packed weight W applied to 2x2 conv positions
#define K9(W, KY, KX)                                   \
    a0 = fma2(pd[(KY)][(KX)],         (W), a0);         \
    a1 = fma2(pd[(KY)][(KX) + 1],     (W), a1);         \
    a2 = fma2(pd[(KY) + 1][(KX)],     (W), a2);         \
    a3 = fma2(pd[(KY) + 1][(KX) + 1], (W), a3);

#define NBLK 296
#define NTILE 1536

// ---------------- dynamic tile queue ----------------------------------------
__device__ int g_ctr;
__global__ void reset_kernel() { if (threadIdx.x == 0) g_ctr = 0; }

// x-halo staging prefetch for tile (img, by0, bx0) into xst (140 rows x 144 cols).
// All 16B chunks fully in-bounds or fully OOB (zero-filled) -- no straddles.
#define PREFETCH_X(IMG, BY0, BX0)                                             \
    {                                                                         \
        const float* xb = x + (size_t)(IMG) * 262144;                         \
        int ry0 = 4 * (BY0) - 6;                                              \
        int xc0a = (4 * (BX0) - 6) & ~3;                                      \
        for (int idx = tid; idx < 140 * 36; idx += 512) {                     \
            int rr = idx / 36, j = idx - rr * 36;                             \
            int gr = ry0 + rr, gc = xc0a + 4 * j;                             \
            bool ok = ((unsigned)gr < 512u) && ((unsigned)gc < 512u);         \
            const float* src = ok ? (xb + (size_t)gr * 512 + gc) : xb;        \
            cp_async16(xst_s + (unsigned int)(rr * 144 + 4 * j) * 4u, src,    \
                       ok ? 16 : 0);                                          \
        }                                                                     \
        cp_commit();                                                          \
    }

// ---------------- Single persistent fused kernel ----------------------------
// grid 296 (2/SM), block 512. Dynamic tile claiming via g_ctr.
// Per tile: wait xst -> phase0 DWT (xst->cAt + own cH/cV) -> phase1 conv1+pool
// -> ins -> phase2 conv2+pool (claims next tile during; ic loop unroll 2)
// -> prefetch next x -> conv3.
__global__ void __launch_bounds__(512, 2)
fused_all_kernel(const float* __restrict__ x,
                 const float* __restrict__ w1, const float* __restrict__ b1,
                 const float* __restrict__ w2, const float* __restrict__ b2,
                 const float* __restrict__ w3, const float* __restrict__ b3,
                 float* __restrict__ out_low, float* __restrict__ out_high) {
    extern __shared__ float sm[];
    float* cAt = sm;                       // 70 * 72 = 5040 floats
    float* ins = sm + 5040;                // max(140*144, 16*1224) = 20160 floats
    float* xst = ins;                      // x staging aliases ins
    ull*   w2p = (ull*)(ins + 20160);      // 640 ull (1280 fl)
    ull*   w1p = w2p + 640;                // 80 ull (160 fl)
    float* tail = (float*)(w1p + 80);
    ull*   b1p = (ull*)tail;               // 8 ull (16 fl) packed conv1 bias pairs
    ull*   b2p = (ull*)(tail + 16);        // 4 ull (8 fl) packed conv2 bias pairs
    float* w3s = tail + 24;                // 32
    float* b3s = tail + 56;                // 4
    float* v4buf = tail + 64;              // 2048 floats
    int*   flg = (int*)(tail + 64 + 2048); // [0]=initial claim, [1]=next claim

    int tid = threadIdx.x;                               // 512 threads
    unsigned int xst_s = (unsigned int)__cvta_generic_to_shared(xst);

    // ---- initial tile claim ----
    if (tid == 0) flg[0] = atomicAdd(&g_ctr, 1);
    __syncthreads();
    int tile = flg[0];

    // ---- prologue prefetch for first tile ----
    if (tile < NTILE) {
        int img0 = tile >> 4;
        int tt0 = tile & 15;
        int by00 = (tt0 >> 2) * 32, bx00 = (tt0 & 3) * 32;
        PREFETCH_X(img0, by00, bx00)
    }

    // ---- weights (once per block) ----
    if (tid < 80) {
        int op = tid / 10, k = tid - op * 10;
        w1p[tid] = (k < 9) ? pack2(w1[(2 * op) * 9 + k], w1[(2 * op + 1) * 9 + k]) : 0ull;
    }
    for (int i = tid; i < 640; i += 512) {
        int op = i / 160;
        int rem = i - op * 160;            // ic*10 + k
        int ic = rem / 10, k = rem - ic * 10;
        w2p[i] = (k < 9) ? pack2(w2[(2 * op) * 144 + ic * 9 + k],
                                 w2[(2 * op + 1) * 144 + ic * 9 + k]) : 0ull;
    }
    if (tid < 8) b1p[tid] = pack2(b1[2 * tid], b1[2 * tid + 1]);
    if (tid >= 8 && tid < 12) b2p[tid - 8] = pack2(b2[2 * (tid - 8)], b2[2 * (tid - 8) + 1]);
    if (tid < 32) w3s[tid] = w3[tid];
    if (tid < 4) b3s[tid] = b3[tid];

    while (tile < NTILE) {
        int img = tile >> 4;
        int tt = tile & 15;
        int by0 = (tt >> 2) * 32, bx0 = (tt & 3) * 32;   // conv2 origin in 128x128
        int cy0 = 2 * by0 - 3, cx0 = 2 * bx0 - 3;        // cA halo origin in 256x256

        cp_wait0();
        __syncthreads();                   // (a) xst staged; v4buf/flg free

        // ---- phase 0: Haar DWT from xst -> cAt + own cH/cV region ----
        {
            float* hb = out_high + (size_t)img * 131072;
            for (int idx = tid; idx < 70 * 70; idx += 512) {
                int r = idx / 70, c = idx - r * 70;
                const float* bp = xst + 2 * r * 144 + 2 * c + 2;
                float2 t = *(const float2*)bp;
                float2 bo = *(const float2*)(bp + 144);
                float a = t.x, b = t.y, cc = bo.x, d = bo.y;
                cAt[r * 72 + c] = (a + b + cc + d) * 0.5f;
                if (r >= 3 && r < 67 && c >= 3 && c < 67) {
                    int o = (cy0 + r) * 256 + (cx0 + c);
                    hb[o]         = (a + b - cc - d) * 0.5f;
                    hb[65536 + o] = (a - b + cc - d) * 0.5f;
                }
            }
        }
        __syncthreads();                   // (b) cAt ready; xst consumed

        // ---- phase 1: t1 tile (34x34 positions x 16 ch) -> ins ----
        for (int pos = tid; pos < 34 * 34; pos += 512) {
            int r = pos / 34, c = pos - r * 34;
            int ty = by0 - 1 + r, tx = bx0 - 1 + c;       // global t1 coords
            float* op_out = ins + r * 36 + c;
            if ((unsigned)ty < 128u && (unsigned)tx < 128u) {
                const float* ip = cAt + 2 * r * 72 + 2 * c;
                ull pd[4][4];
#pragma unroll
                for (int rr = 0; rr < 4; rr++) {
                    float2 u0 = *(const float2*)(ip + rr * 72);
                    float2 u1 = *(const float2*)(ip + rr * 72 + 2);
                    pd[rr][0] = dup2(u0.x); pd[rr][1] = dup2(u0.y);
                    pd[rr][2] = dup2(u1.x); pd[rr][3] = dup2(u1.y);
                }
#pragma unroll
                for (int op = 0; op < 8; op++) {
                    ull bb = b1p[op];
                    ull a0 = bb, a1 = bb, a2 = bb, a3 = bb;
                    const ull* wp = w1p + op * 10;
                    ulonglong2 w01 = *(const ulonglong2*)wp;
                    ulonglong2 w23 = *(const ulonglong2*)(wp + 2);
                    ulonglong2 w45 = *(const ulonglong2*)(wp + 4);
                    ulonglong2 w67 = *(const ulonglong2*)(wp + 6);
                    ull w8 = wp[8];
                    K9(w01.x, 0, 0) K9(w01.y, 0, 1) K9(w23.x, 0, 2)
                    K9(w23.y, 1, 0) K9(w45.x, 1, 1) K9(w45.y, 1, 2)
                    K9(w67.x, 2, 0) K9(w67.y, 2, 1) K9(w8,    2, 2)
                    float s0l, s0h, s1l, s1h, s2l, s2h, s3l, s3h;
                    unpack2(a0, s0l, s0h); unpack2(a1, s1l, s1h);
                    unpack2(a2, s2l, s2h); unpack2(a3, s3l, s3h);
                    float ml = fmaxf(fmaxf(s0l, s1l), fmaxf(s2l, s3l));
                    float mh = fmaxf(fmaxf(s0h, s1h), fmaxf(s2h, s3h));
                    op_out[(2 * op) * 1224]     = fmaxf(ml, 0.f);
                    op_out[(2 * op + 1) * 1224] = fmaxf(mh, 0.f);
                }
            } else {
#pragma unroll
                for (int ic = 0; ic < 16; ic++) op_out[ic * 1224] = 0.f;
            }
        }
        __syncthreads();                   // (c) ins ready

        // ---- claim next tile (latency hidden under phase 2) ----
        if (tid == 0) flg[1] = atomicAdd(&g_ctr, 1);

        // ---- phase 2: conv2 + relu + pool (oc split across 2 groups) ----
        int pix = tid & 255, g = tid >> 8;
        int tyx = pix & 15, tyy = pix >> 4;
        int ly = 2 * tyy, lx = 2 * tyx;
        const ull* wg = w2p + (2 * g) * 160;
        ull acc[2][4];
#pragma unroll
        for (int op2 = 0; op2 < 2; op2++) {
            ull bb = b2p[2 * g + op2];
            acc[op2][0] = bb; acc[op2][1] = bb; acc[op2][2] = bb; acc[op2][3] = bb;
        }

#pragma unroll 2
        for (int ic = 0; ic < 16; ic++) {
            const float* ip = ins + ic * 1224 + ly * 36 + lx;
            ull pd[4][4];
#pragma unroll
            for (int rr = 0; rr < 4; rr++) {
                float2 u0 = *(const float2*)(ip + rr * 36);
                float2 u1 = *(const float2*)(ip + rr * 36 + 2);
                pd[rr][0] = dup2(u0.x); pd[rr][1] = dup2(u0.y);
                pd[rr][2] = dup2(u1.x); pd[rr][3] = dup2(u1.y);
            }
#pragma unroll
            for (int op2 = 0; op2 < 2; op2++) {
                const ull* wp = wg + op2 * 160 + ic * 10;
                ulonglong2 w01 = *(const ulonglong2*)wp;
                ulonglong2 w23 = *(const ulonglong2*)(wp + 2);
                ulonglong2 w45 = *(const ulonglong2*)(wp + 4);
                ulonglong2 w67 = *(const ulonglong2*)(wp + 6);
                ull w8 = wp[8];
                ull a0 = acc[op2][0], a1 = acc[op2][1], a2 = acc[op2][2], a3 = acc[op2][3];
                K9(w01.x, 0, 0) K9(w01.y, 0, 1) K9(w23.x, 0, 2)
                K9(w23.y, 1, 0) K9(w45.x, 1, 1) K9(w45.y, 1, 2)
                K9(w67.x, 2, 0) K9(w67.y, 2, 1) K9(w8,    2, 2)
                acc[op2][0] = a0; acc[op2][1] = a1; acc[op2][2] = a2; acc[op2][3] = a3;
            }
        }

        float v4[4];
#pragma unroll
        for (int op2 = 0; op2 < 2; op2++) {
            float s0l, s0h, s1l, s1h, s2l, s2h, s3l, s3h;
            unpack2(acc[op2][0], s0l, s0h); unpack2(acc[op2][1], s1l, s1h);
            unpack2(acc[op2][2], s2l, s2h); unpack2(acc[op2][3], s3l, s3h);
            float ml = fmaxf(fmaxf(s0l, s1l), fmaxf(s2l, s3l));
            float mh = fmaxf(fmaxf(s0h, s1h), fmaxf(s2h, s3h));
            v4[2 * op2]     = fmaxf(ml, 0.f);
            v4[2 * op2 + 1] = fmaxf(mh, 0.f);
        }
        *(float4*)(v4buf + pix * 8 + 4 * g) = make_float4(v4[0], v4[1], v4[2], v4[3]);
        __syncthreads();                   // (d) ins dead; v4buf + flg[1] ready

        int ntile = flg[1];

        // ---- prefetch next tile's x halo into ins (overlaps conv3) ----
        if (ntile < NTILE) {
            int nimg = ntile >> 4;
            int ntt = ntile & 15;
            int nby = (ntt >> 2) * 32, nbx = (ntt & 3) * 32;
            PREFETCH_X(nimg, nby, nbx)
        }

        // ---- phase 3: conv3 (8->4, 1x1): 512 threads, 2 outputs each ----
        {
            int p = tid >> 1;                    // pixel 0..255
            int half = (tid & 1) * 2;            // o3 in {half, half+1}
            float4 lo4 = *(const float4*)(v4buf + p * 8);
            float4 hi4 = *(const float4*)(v4buf + p * 8 + 4);
            float v8[8] = {lo4.x, lo4.y, lo4.z, lo4.w, hi4.x, hi4.y, hi4.z, hi4.w};
            int oy = (by0 >> 1) + (p >> 4);
            int ox = (bx0 >> 1) + (p & 15);
            float* ob = out_low + (size_t)img * 4 * 4096 + oy * 64 + ox;
#pragma unroll
            for (int j = 0; j < 2; j++) {
                int o3 = half + j;
                float s = b3s[o3];
#pragma unroll
                for (int ic = 0; ic < 8; ic++) s += v8[ic] * w3s[o3 * 8 + ic];
                ob[o3 * 4096] = s;
            }
        }

        tile = ntile;
        // loop top: cp_wait0 + syncthreads orders xst staging & v4buf reuse
    }
}

// ---------------------------------------------------------------------------
extern "C" void kernel_launch(void* const* d_in, const int* in_sizes, int n_in,
                              void* d_out, int out_size) {
    const float* x  = (const float*)d_in[0];
    const float* w1 = (const float*)d_in[1];
    const float* b1 = (const float*)d_in[2];
    const float* w2 = (const float*)d_in[3];
    const float* b2 = (const float*)d_in[4];
    const float* w3 = (const float*)d_in[5];
    const float* b3 = (const float*)d_in[6];
    float* out = (float*)d_out;

    const int LOW_SIZE = 96 * 4 * 64 * 64;                               // 1,572,864
    const int SMEM_F = (5040 + 20160 + 1280 + 160 + 64 + 2048 + 4) * 4;  // 115,024 B

    cudaFuncSetAttribute(fused_all_kernel, cudaFuncAttributeMaxDynamicSharedMemorySize, SMEM_F);

    reset_kernel<<<1, 32>>>();
    fused_all_kernel<<<NBLK, 512, SMEM_F>>>(x, w1, b1, w2, b2, w3, b3,
                                            out, out + LOW_SIZE);
}

// round 16
// speedup vs baseline: 1.2081x; 1.0186x over previous
#include <cuda_runtime.h>
#include <cstdint>

typedef unsigned long long ull;

// ---------------- packed f32x2 helpers (Blackwell FFMA2 path) ---------------
__device__ __forceinline__ ull pack2(float lo, float hi) {
    ull r; asm("mov.b64 %0, {%1, %2};" : "=l"(r) : "f"(lo), "f"(hi)); return r;
}
__device__ __forceinline__ ull dup2(float v) {
    ull r; asm("mov.b64 %0, {%1, %1};" : "=l"(r) : "f"(v)); return r;
}
__device__ __forceinline__ void unpack2(ull v, float& lo, float& hi) {
    asm("mov.b64 {%0, %1}, %2;" : "=f"(lo), "=f"(hi) : "l"(v));
}
__device__ __forceinline__ ull fma2(ull a, ull b, ull c) {
    ull d; asm("fma.rn.f32x2 %0, %1, %2, %3;" : "=l"(d) : "l"(a), "l"(b), "l"(c)); return d;
}
__device__ __forceinline__ void cp_async16(unsigned int saddr, const void* gptr, int src_sz) {
    asm volatile("cp.async.cg.shared.global [%0], [%1], 16, %2;"
                 :: "r"(saddr), "l"(gptr), "r"(src_sz));
}
__device__ __forceinline__ void cp_commit() { asm volatile("cp.async.commit_group;"); }
__device__ __forceinline__ void cp_wait0()  { asm volatile("cp.async.wait_group 0;"); }

// 9-tap accumulate macro: packed weight W applied to 2x2 conv positions
#define K9(W, KY, KX)                                   \
    a0 = fma2(pd[(KY)][(KX)],         (W), a0);         \
    a1 = fma2(pd[(KY)][(KX) + 1],     (W), a1);         \
    a2 = fma2(pd[(KY) + 1][(KX)],     (W), a2);         \
    a3 = fma2(pd[(KY) + 1][(KX) + 1], (W), a3);

#define NBLK 296
#define NTILE 1536

// ---------------- dynamic tile queue ----------------------------------------
__device__ int g_ctr;
__global__ void reset_kernel() { if (threadIdx.x == 0) g_ctr = 0; }

// x-halo staging prefetch for tile (img, by0, bx0) into xst (140 rows x 144 cols).
// All 16B chunks fully in-bounds or fully OOB (zero-filled) -- no straddles.
#define PREFETCH_X(IMG, BY0, BX0)                                             \
    {                                                                         \
        const float* xb = x + (size_t)(IMG) * 262144;                         \
        int ry0 = 4 * (BY0) - 6;                                              \
        int xc0a = (4 * (BX0) - 6) & ~3;                                      \
        for (int idx = tid; idx < 140 * 36; idx += 512) {                     \
            int rr = idx / 36, j = idx - rr * 36;                             \
            int gr = ry0 + rr, gc = xc0a + 4 * j;                             \
            bool ok = ((unsigned)gr < 512u) && ((unsigned)gc < 512u);         \
            const float* src = ok ? (xb + (size_t)gr * 512 + gc) : xb;        \
            cp_async16(xst_s + (unsigned int)(rr * 144 + 4 * j) * 4u, src,    \
                       ok ? 16 : 0);                                          \
        }                                                                     \
        cp_commit();                                                          \
    }

// ---------------- Single persistent fused kernel ----------------------------
// grid 296 (2/SM), block 512. Dynamic tile claiming via g_ctr.
// Per tile: wait xst -> phase0 DWT (paired cols, float4 loads) -> phase1
// conv1+pool -> ins -> phase2 conv2+pool (claims next tile) -> prefetch -> conv3.
__global__ void __launch_bounds__(512, 2)
fused_all_kernel(const float* __restrict__ x,
                 const float* __restrict__ w1, const float* __restrict__ b1,
                 const float* __restrict__ w2, const float* __restrict__ b2,
                 const float* __restrict__ w3, const float* __restrict__ b3,
                 float* __restrict__ out_low, float* __restrict__ out_high) {
    extern __shared__ float sm[];
    float* cAt = sm;                       // 70 * 72 = 5040 floats
    float* ins = sm + 5040;                // max(140*144, 16*1224) = 20160 floats
    float* xst = ins;                      // x staging aliases ins
    ull*   w2p = (ull*)(ins + 20160);      // 640 ull (1280 fl)
    ull*   w1p = w2p + 640;                // 80 ull (160 fl)
    float* tail = (float*)(w1p + 80);
    ull*   b1p = (ull*)tail;               // 8 ull packed conv1 bias pairs
    ull*   b2p = (ull*)(tail + 16);        // 4 ull packed conv2 bias pairs
    float* w3s = tail + 24;                // 32
    float* b3s = tail + 56;                // 4
    float* v4buf = tail + 64;              // 2048 floats
    int*   flg = (int*)(tail + 64 + 2048); // [0]=initial claim, [1]=next claim

    int tid = threadIdx.x;                               // 512 threads
    unsigned int xst_s = (unsigned int)__cvta_generic_to_shared(xst);

    // ---- initial tile claim ----
    if (tid == 0) flg[0] = atomicAdd(&g_ctr, 1);
    __syncthreads();
    int tile = flg[0];

    // ---- prologue prefetch for first tile ----
    if (tile < NTILE) {
        int img0 = tile >> 4;
        int tt0 = tile & 15;
        int by00 = (tt0 >> 2) * 32, bx00 = (tt0 & 3) * 32;
        PREFETCH_X(img0, by00, bx00)
    }

    // ---- weights (once per block) ----
    if (tid < 80) {
        int op = tid / 10, k = tid - op * 10;
        w1p[tid] = (k < 9) ? pack2(w1[(2 * op) * 9 + k], w1[(2 * op + 1) * 9 + k]) : 0ull;
    }
    for (int i = tid; i < 640; i += 512) {
        int op = i / 160;
        int rem = i - op * 160;            // ic*10 + k
        int ic = rem / 10, k = rem - ic * 10;
        w2p[i] = (k < 9) ? pack2(w2[(2 * op) * 144 + ic * 9 + k],
                                 w2[(2 * op + 1) * 144 + ic * 9 + k]) : 0ull;
    }
    if (tid < 8) b1p[tid] = pack2(b1[2 * tid], b1[2 * tid + 1]);
    if (tid >= 8 && tid < 12) b2p[tid - 8] = pack2(b2[2 * (tid - 8)], b2[2 * (tid - 8) + 1]);
    if (tid < 32) w3s[tid] = w3[tid];
    if (tid < 4) b3s[tid] = b3[tid];

    while (tile < NTILE) {
        int img = tile >> 4;
        int tt = tile & 15;
        int by0 = (tt >> 2) * 32, bx0 = (tt & 3) * 32;   // conv2 origin in 128x128
        int cy0 = 2 * by0 - 3, cx0 = 2 * bx0 - 3;        // cA halo origin in 256x256

        cp_wait0();
        __syncthreads();                   // (a) xst staged; v4buf/flg free

        // ---- phase 0: Haar DWT from xst -> cAt + own cH/cV region ----
        {
            float* hb = out_high + (size_t)img * 131072;
            // main: odd-c pairs (c, c+1), c = 2*cp+1, cp in 0..33 -> cols 1..68
            for (int u = tid; u < 70 * 34; u += 512) {
                int r = u / 34, cp = u - r * 34;
                int c = 2 * cp + 1;
                // cols 2c+2 .. 2c+5 are 16B aligned (2c+2 = 4cp+4)
                const float* bp = xst + 2 * r * 144 + 2 * c + 2;
                float4 t = *(const float4*)bp;
                float4 bo = *(const float4*)(bp + 144);
                float cA0 = (t.x + t.y + bo.x + bo.y) * 0.5f;
                float cA1 = (t.z + t.w + bo.z + bo.w) * 0.5f;
                cAt[r * 72 + c]     = cA0;
                cAt[r * 72 + c + 1] = cA1;
                if (r >= 3 && r < 67 && c >= 3 && c <= 65) {
                    float cH0 = (t.x + t.y - bo.x - bo.y) * 0.5f;
                    float cV0 = (t.x - t.y + bo.x - bo.y) * 0.5f;
                    float cH1 = (t.z + t.w - bo.z - bo.w) * 0.5f;
                    float cV1 = (t.z - t.w + bo.z - bo.w) * 0.5f;
                    int o = (cy0 + r) * 256 + (cx0 + c);   // cx0 odd + c odd = even
                    *(float2*)(hb + o)         = make_float2(cH0, cH1);
                    *(float2*)(hb + 65536 + o) = make_float2(cV0, cV1);
                }
            }
            // edges: c = 0 and c = 69 (never interior -> cAt only)
            for (int u2 = tid; u2 < 140; u2 += 512) {
                int r = u2 >> 1;
                int c = (u2 & 1) ? 69 : 0;
                const float* bp = xst + 2 * r * 144 + 2 * c + 2;
                float2 t = *(const float2*)bp;
                float2 bo = *(const float2*)(bp + 144);
                cAt[r * 72 + c] = (t.x + t.y + bo.x + bo.y) * 0.5f;
            }
        }
        __syncthreads();                   // (b) cAt ready; xst consumed

        // ---- phase 1: t1 tile (34x34 positions x 16 ch) -> ins ----
        for (int pos = tid; pos < 34 * 34; pos += 512) {
            int r = pos / 34, c = pos - r * 34;
            int ty = by0 - 1 + r, tx = bx0 - 1 + c;       // global t1 coords
            float* op_out = ins + r * 36 + c;
            if ((unsigned)ty < 128u && (unsigned)tx < 128u) {
                const float* ip = cAt + 2 * r * 72 + 2 * c;
                ull pd[4][4];
#pragma unroll
                for (int rr = 0; rr < 4; rr++) {
                    float2 u0 = *(const float2*)(ip + rr * 72);
                    float2 u1 = *(const float2*)(ip + rr * 72 + 2);
                    pd[rr][0] = dup2(u0.x); pd[rr][1] = dup2(u0.y);
                    pd[rr][2] = dup2(u1.x); pd[rr][3] = dup2(u1.y);
                }
#pragma unroll
                for (int op = 0; op < 8; op++) {
                    ull bb = b1p[op];
                    ull a0 = bb, a1 = bb, a2 = bb, a3 = bb;
                    const ull* wp = w1p + op * 10;
                    ulonglong2 w01 = *(const ulonglong2*)wp;
                    ulonglong2 w23 = *(const ulonglong2*)(wp + 2);
                    ulonglong2 w45 = *(const ulonglong2*)(wp + 4);
                    ulonglong2 w67 = *(const ulonglong2*)(wp + 6);
                    ull w8 = wp[8];
                    K9(w01.x, 0, 0) K9(w01.y, 0, 1) K9(w23.x, 0, 2)
                    K9(w23.y, 1, 0) K9(w45.x, 1, 1) K9(w45.y, 1, 2)
                    K9(w67.x, 2, 0) K9(w67.y, 2, 1) K9(w8,    2, 2)
                    float s0l, s0h, s1l, s1h, s2l, s2h, s3l, s3h;
                    unpack2(a0, s0l, s0h); unpack2(a1, s1l, s1h);
                    unpack2(a2, s2l, s2h); unpack2(a3, s3l, s3h);
                    float ml = fmaxf(fmaxf(s0l, s1l), fmaxf(s2l, s3l));
                    float mh = fmaxf(fmaxf(s0h, s1h), fmaxf(s2h, s3h));
                    op_out[(2 * op) * 1224]     = fmaxf(ml, 0.f);
                    op_out[(2 * op + 1) * 1224] = fmaxf(mh, 0.f);
                }
            } else {
#pragma unroll
                for (int ic = 0; ic < 16; ic++) op_out[ic * 1224] = 0.f;
            }
        }
        __syncthreads();                   // (c) ins ready

        // ---- claim next tile (latency hidden under phase 2) ----
        if (tid == 0) flg[1] = atomicAdd(&g_ctr, 1);

        // ---- phase 2: conv2 + relu + pool (oc split across 2 groups) ----
        int pix = tid & 255, g = tid >> 8;
        int tyx = pix & 15, tyy = pix >> 4;
        int ly = 2 * tyy, lx = 2 * tyx;
        const ull* wg = w2p + (2 * g) * 160;
        ull acc[2][4];
#pragma unroll
        for (int op2 = 0; op2 < 2; op2++) {
            ull bb = b2p[2 * g + op2];
            acc[op2][0] = bb; acc[op2][1] = bb; acc[op2][2] = bb; acc[op2][3] = bb;
        }

#pragma unroll 2
        for (int ic = 0; ic < 16; ic++) {
            const float* ip = ins + ic * 1224 + ly * 36 + lx;
            ull pd[4][4];
#pragma unroll
            for (int rr = 0; rr < 4; rr++) {
                float2 u0 = *(const float2*)(ip + rr * 36);
                float2 u1 = *(const float2*)(ip + rr * 36 + 2);
                pd[rr][0] = dup2(u0.x); pd[rr][1] = dup2(u0.y);
                pd[rr][2] = dup2(u1.x); pd[rr][3] = dup2(u1.y);
            }
#pragma unroll
            for (int op2 = 0; op2 < 2; op2++) {
                const ull* wp = wg + op2 * 160 + ic * 10;
                ulonglong2 w01 = *(const ulonglong2*)wp;
                ulonglong2 w23 = *(const ulonglong2*)(wp + 2);
                ulonglong2 w45 = *(const ulonglong2*)(wp + 4);
                ulonglong2 w67 = *(const ulonglong2*)(wp + 6);
                ull w8 = wp[8];
                ull a0 = acc[op2][0], a1 = acc[op2][1], a2 = acc[op2][2], a3 = acc[op2][3];
                K9(w01.x, 0, 0) K9(w01.y, 0, 1) K9(w23.x, 0, 2)
                K9(w23.y, 1, 0) K9(w45.x, 1, 1) K9(w45.y, 1, 2)
                K9(w67.x, 2, 0) K9(w67.y, 2, 1) K9(w8,    2, 2)
                acc[op2][0] = a0; acc[op2][1] = a1; acc[op2][2] = a2; acc[op2][3] = a3;
            }
        }

        float v4[4];
#pragma unroll
        for (int op2 = 0; op2 < 2; op2++) {
            float s0l, s0h, s1l, s1h, s2l, s2h, s3l, s3h;
            unpack2(acc[op2][0], s0l, s0h); unpack2(acc[op2][1], s1l, s1h);
            unpack2(acc[op2][2], s2l, s2h); unpack2(acc[op2][3], s3l, s3h);
            float ml = fmaxf(fmaxf(s0l, s1l), fmaxf(s2l, s3l));
            float mh = fmaxf(fmaxf(s0h, s1h), fmaxf(s2h, s3h));
            v4[2 * op2]     = fmaxf(ml, 0.f);
            v4[2 * op2 + 1] = fmaxf(mh, 0.f);
        }
        *(float4*)(v4buf + pix * 8 + 4 * g) = make_float4(v4[0], v4[1], v4[2], v4[3]);
        __syncthreads();                   // (d) ins dead; v4buf + flg[1] ready

        int ntile = flg[1];

        // ---- prefetch next tile's x halo into ins (overlaps conv3) ----
        if (ntile < NTILE) {
            int nimg = ntile >> 4;
            int ntt = ntile & 15;
            int nby = (ntt >> 2) * 32, nbx = (ntt & 3) * 32;
            PREFETCH_X(nimg, nby, nbx)
        }

        // ---- phase 3: conv3 (8->4, 1x1): 512 threads, 2 outputs each ----
        {
            int p = tid >> 1;                    // pixel 0..255
            int half = (tid & 1) * 2;            // o3 in {half, half+1}
            float4 lo4 = *(const float4*)(v4buf + p * 8);
            float4 hi4 = *(const float4*)(v4buf + p * 8 + 4);
            float v8[8] = {lo4.x, lo4.y, lo4.z, lo4.w, hi4.x, hi4.y, hi4.z, hi4.w};
            int oy = (by0 >> 1) + (p >> 4);
            int ox = (bx0 >> 1) + (p & 15);
            float* ob = out_low + (size_t)img * 4 * 4096 + oy * 64 + ox;
#pragma unroll
            for (int j = 0; j < 2; j++) {
                int o3 = half + j;
                float s = b3s[o3];
#pragma unroll
                for (int ic = 0; ic < 8; ic++) s += v8[ic] * w3s[o3 * 8 + ic];
                ob[o3 * 4096] = s;
            }
        }

        tile = ntile;
        // loop top: cp_wait0 + syncthreads orders xst staging & v4buf reuse
    }
}

// ---------------------------------------------------------------------------
extern "C" void kernel_launch(void* const* d_in, const int* in_sizes, int n_in,
                              void* d_out, int out_size) {
    const float* x  = (const float*)d_in[0];
    const float* w1 = (const float*)d_in[1];
    const float* b1 = (const float*)d_in[2];
    const float* w2 = (const float*)d_in[3];
    const float* b2 = (const float*)d_in[4];
    const float* w3 = (const float*)d_in[5];
    const float* b3 = (const float*)d_in[6];
    float* out = (float*)d_out;

    const int LOW_SIZE = 96 * 4 * 64 * 64;                               // 1,572,864
    const int SMEM_F = (5040 + 20160 + 1280 + 160 + 64 + 2048 + 4) * 4;  // 115,024 B

    cudaFuncSetAttribute(fused_all_kernel, cudaFuncAttributeMaxDynamicSharedMemorySize, SMEM_F);

    reset_kernel<<<1, 32>>>();
    fused_all_kernel<<<NBLK, 512, SMEM_F>>>(x, w1, b1, w2, b2, w3, b3,
                                            out, out + LOW_SIZE);
}